// round 11
// baseline (speedup 1.0000x reference)
#include <cuda_runtime.h>

typedef unsigned long long ull;

#define TSTEPS   512
#define NDIM     512
#define NIN      6
#define CLUSTER  8
#define TILE_B   8
#define TILE_N   64
#define NTHREADS 256
#define K4       128      // 512/4 float4-chunks along k

#define W_OFF     0
#define W_BYTES   (K4 * TILE_N * 16)        // 131072
#define BUF_OFF   (W_OFF + W_BYTES)         // 131072 (2 x 16KB, parity)
#define BUF_BYTES 16384
#define STG_OFF   (BUF_OFF + 2 * BUF_BYTES) // 163840 (2 x 2KB, parity)
#define STG_BYTES 2048
#define WINS_OFF  (STG_OFF + 2 * STG_BYTES) // 167936 (64 x 8 floats)
#define BREC_OFF  (WINS_OFF + TILE_N * 8 * 4) // 169984 (64 floats)
#define MBAR_OFF  (BREC_OFF + TILE_N * 4)   // 170240 (2 x 8B)
#define SMEM_BYTES (MBAR_OFF + 64)

__device__ __forceinline__ void ffma2(ull &acc, ull a, ull b) {
    asm("fma.rn.f32x2 %0, %1, %2, %0;" : "+l"(acc) : "l"(a), "l"(b));
}
__device__ __forceinline__ float2 unpack2(ull v) {
    float2 r;
    asm("mov.b64 {%0,%1}, %2;" : "=f"(r.x), "=f"(r.y) : "l"(v));
    return r;
}
__device__ __forceinline__ float tf32r(float x) {
    float r;
    asm("cvt.rna.tf32.f32 %0, %1;" : "=f"(r) : "f"(x));
    return r;
}
__device__ __forceinline__ float4 tf32r4(float4 v) {
    v.x = tf32r(v.x); v.y = tf32r(v.y); v.z = tf32r(v.z); v.w = tf32r(v.w);
    return v;
}
__device__ __forceinline__ unsigned mapa_sh(unsigned addr, unsigned rank) {
    unsigned r;
    asm("mapa.shared::cluster.u32 %0, %1, %2;" : "=r"(r) : "r"(addr), "r"(rank));
    return r;
}
__device__ __forceinline__ void mbar_init(unsigned mb, unsigned cnt) {
    asm volatile("mbarrier.init.shared.b64 [%0], %1;" :: "r"(mb), "r"(cnt) : "memory");
}
__device__ __forceinline__ void mbar_arm(unsigned mb, unsigned tx) {
    asm volatile("mbarrier.arrive.expect_tx.shared.b64 _, [%0], %1;" :: "r"(mb), "r"(tx) : "memory");
}
__device__ __forceinline__ void mbar_wait_parity(unsigned mbar, unsigned parity) {
    unsigned done;
    asm volatile(
        "{\n\t.reg .pred p;\n\t"
        "mbarrier.try_wait.parity.acquire.cta.shared::cta.b64 p, [%1], %2;\n\t"
        "selp.b32 %0, 1, 0, p;\n\t}"
        : "=r"(done) : "r"(mbar), "r"(parity) : "memory");
    if (!done) {
        asm volatile(
            "{\n\t.reg .pred P1;\n\t"
            "WL_%=:\n\t"
            "mbarrier.try_wait.parity.acquire.cta.shared::cta.b64 P1, [%0], %1, 0x989680;\n\t"
            "@P1 bra.uni WD_%=;\n\t"
            "bra.uni WL_%=;\n\t"
            "WD_%=:\n\t}"
            :: "r"(mbar), "r"(parity) : "memory");
    }
}
__device__ __forceinline__ void dsmem_copy2k(unsigned dst, unsigned src, unsigned mb) {
    asm volatile(
        "cp.async.bulk.shared::cluster.shared::cta.mbarrier::complete_tx::bytes [%0], [%1], %2, [%3];"
        :: "r"(dst), "r"(src), "r"((unsigned)STG_BYTES), "r"(mb) : "memory");
}

__global__ void __launch_bounds__(NTHREADS, 1) __cluster_dims__(CLUSTER, 1, 1)
rnn_cluster_kernel(const float* __restrict__ u,
                   const float* __restrict__ inoise,
                   const float* __restrict__ rnoise,
                   const float* __restrict__ Wrec,
                   const float* __restrict__ brec,
                   const float* __restrict__ Win,
                   float* __restrict__ out)
{
    extern __shared__ char smem[];
    ulonglong2* Wq2  = (ulonglong2*)(smem + W_OFF);   // [K4][64] tf32-rounded, 16B = 4 k-values of col n
    float4*     Wq4  = (float4*)Wq2;
    float*      WinS = (float*)(smem + WINS_OFF);     // [64][8] tf32-rounded
    float*      brecS= (float*)(smem + BREC_OFF);     // [64]

    const int tid  = threadIdx.x;
    unsigned rank;
    asm("mov.u32 %0, %%cluster_ctarank;" : "=r"(rank));
    const int bg   = blockIdx.x >> 3;                 // batch group = cluster id (16)

    const unsigned smem_base = (unsigned)__cvta_generic_to_shared(smem);
    const unsigned mbar_base = smem_base + MBAR_OFF;  // mbar[i] at +8*i
    const unsigned buf_base  = smem_base + BUF_OFF;
    const unsigned stg_base  = smem_base + STG_OFF;

    // thread mapping: warp w owns n_local [w*8, w*8+8); lane: b = lane>>2 (0..7), np = lane&3
    const int w    = tid >> 5, lane = tid & 31;
    const int b    = lane >> 2;
    const int np   = lane & 3;
    const int n_l0 = w * 8 + 2 * np;                  // local n pair (n_l0, n_l0+1)
    const int bG   = bg * TILE_B + b;                 // global batch row
    const int nG0  = rank * TILE_N + n_l0;            // global n

    // ---------------- init: W slice (tf32), Win, brec, mbars, zero buf[0] ----------------
    const float4* WrecF4 = (const float4*)Wrec;
    for (int idx = tid; idx < TILE_N * K4; idx += NTHREADS) {
        int r = idx >> 7, k4 = idx & (K4 - 1);        // r = n_local row 0..63
        Wq4[k4 * TILE_N + r] = tf32r4(__ldg(&WrecF4[(rank * TILE_N + r) * K4 + k4]));
    }
    for (int idx = tid; idx < TILE_N * NIN; idx += NTHREADS) {
        int r = idx / NIN, i = idx - r * NIN;
        WinS[r * 8 + i] = tf32r(Win[(rank * TILE_N + r) * NIN + i]);
    }
    if (tid < TILE_N) brecS[tid] = brec[rank * TILE_N + tid];
    // zero h_0 buffer (buf parity 0), 16KB
    for (int idx = tid; idx < BUF_BYTES / 16; idx += NTHREADS)
        ((float4*)(smem + BUF_OFF))[idx] = make_float4(0.f, 0.f, 0.f, 0.f);
    if (tid == 0) {
        mbar_init(mbar_base + 0, 1);
        mbar_init(mbar_base + 8, 1);
        mbar_arm(mbar_base + 0, CLUSTER * STG_BYTES); // arm phase 0 of both
        mbar_arm(mbar_base + 8, CLUSTER * STG_BYTES);
    }
    __syncthreads();
    asm volatile("barrier.cluster.arrive.aligned;" ::: "memory");
    asm volatile("barrier.cluster.wait.aligned;" ::: "memory");

    // out[:, 0, :] = 0
    {
        float2 z = make_float2(0.f, 0.f);
        ((float2*)out)[(((size_t)bG * TSTEPS) * NDIM + nG0) >> 1] = z;
    }

    float hp0 = 0.f, hp1 = 0.f;     // exact h_{s-1} for the leak term (this thread's outputs)
    int p0 = 0, p1 = 0;             // mbar wait parities

    for (int s = 1; s < TSTEPS; ++s) {
        // ---- step-local inputs (independent of h), issued before the wait ----
        float2 rn = __ldg((const float2*)(rnoise + ((size_t)bG * TSTEPS + (s - 1)) * NDIM + nG0));
        float v[NIN];
        {
            const float* ub = u      + ((size_t)bG * TSTEPS + (s - 1)) * NIN;
            const float* nb = inoise + ((size_t)bG * TSTEPS + (s - 1)) * NIN;
            #pragma unroll
            for (int i = 0; i < NIN; ++i)
                v[i] = tf32r(__ldg(&ub[i]) + 0.6324555320336759f * __ldg(&nb[i]));
        }

        // ---- wait for all 8 chunks of h_{s-1} (DSMEM copies into buf[(s-1)&1]) ----
        if (s > 1) {
            int idx = (s - 1) & 1;
            unsigned mb = mbar_base + (unsigned)(idx << 3);
            mbar_wait_parity(mb, (unsigned)(idx ? p1 : p0));
            if (idx) p1 ^= 1; else p0 ^= 1;
            if (tid == 0) mbar_arm(mb, CLUSTER * STG_BYTES);  // re-arm for its next use
        }

        // ---- GEMM: full k per thread, 1b x 2n, f32x2 packed FMA ----
        // buf layout: [chunk r][8 b][16 k4l] float4, swizzled slot = k4l ^ b
        ull a0 = 0ull, a1 = 0ull;
        {
            const char* bufb = smem + BUF_OFF + ((s - 1) & 1) * BUF_BYTES;
            const ulonglong2* Wt = Wq2 + n_l0;
            #pragma unroll 2
            for (int r = 0; r < CLUSTER; ++r) {
                const char* hc = bufb + r * 2048 + b * 256;
                const ulonglong2* Wc = Wt + (r * 16) * TILE_N;
                #pragma unroll
                for (int j = 0; j < 16; ++j) {
                    ulonglong2 h  = *(const ulonglong2*)(hc + ((j ^ b) << 4));
                    ulonglong2 w0 = Wc[j * TILE_N];
                    ulonglong2 w1 = Wc[j * TILE_N + 1];
                    ffma2(a0, h.x, w0.x); ffma2(a0, h.y, w0.y);
                    ffma2(a1, h.x, w1.x); ffma2(a1, h.y, w1.y);
                }
            }
        }
        float2 e0 = unpack2(a0), e1 = unpack2(a1);
        float f0 = e0.x + e0.y, f1 = e1.x + e1.y;

        // ---- input projection (IN=6, TF32 operands) ----
        float in0 = 0.f, in1 = 0.f;
        #pragma unroll
        for (int i = 0; i < NIN; ++i) {
            in0 += v[i] * WinS[n_l0 * 8 + i];
            in1 += v[i] * WinS[(n_l0 + 1) * 8 + i];
        }

        float pre0 = (f0 + brecS[n_l0])     + in0;
        float pre1 = (f1 + brecS[n_l0 + 1]) + in1;
        float h0 = 0.8f * hp0 + 0.2f * (fmaxf(pre0, 0.f) + rn.x);
        float h1 = 0.8f * hp1 + 0.2f * (fmaxf(pre1, 0.f) + rn.y);
        hp0 = h0; hp1 = h1;

        if (s < TSTEPS - 1) {
            // ---- stage TF32-rounded h_s in consumer chunk layout (swizzled) ----
            // chunk layout: [b][16 float4], slot = (n_l>>2) ^ b, sub-offset (n_l&3)*4
            char* stg = smem + STG_OFF + (s & 1) * STG_BYTES;
            *(float2*)(stg + b * 256 + (((n_l0 >> 2) ^ b) << 4) + (n_l0 & 3) * 4)
                = make_float2(tf32r(h0), tf32r(h1));
            __syncthreads();

            // ---- publish: 8 parallel DSMEM bulk copies (lane r -> cluster rank r) ----
            if (tid < CLUSTER) {
                asm volatile("fence.proxy.async;" ::: "memory");
                unsigned src = stg_base + (unsigned)((s & 1) * STG_BYTES);
                unsigned dst = mapa_sh(buf_base + (unsigned)((s & 1) * BUF_BYTES) + rank * STG_BYTES,
                                       (unsigned)tid);
                unsigned mb  = mapa_sh(mbar_base + (unsigned)((s & 1) << 3), (unsigned)tid);
                dsmem_copy2k(dst, src, mb);
            }
        }

        // ---- out write (off the inter-CTA critical path) ----
        ((float2*)out)[(((size_t)bG * TSTEPS + s) * NDIM + nG0) >> 1] = make_float2(h0, h1);
    }

    // keep cluster SMEM alive until every CTA's inbound/outbound traffic is settled
    asm volatile("barrier.cluster.arrive.aligned;" ::: "memory");
    asm volatile("barrier.cluster.wait.aligned;" ::: "memory");
}

extern "C" void kernel_launch(void* const* d_in, const int* in_sizes, int n_in,
                              void* d_out, int out_size) {
    const float* u      = (const float*)d_in[0];
    const float* inoise = (const float*)d_in[1];
    const float* rnoise = (const float*)d_in[2];
    const float* Wrec   = (const float*)d_in[3];
    const float* brec   = (const float*)d_in[4];
    const float* Win    = (const float*)d_in[5];
    float* out = (float*)d_out;

    cudaFuncSetAttribute(rnn_cluster_kernel,
                         cudaFuncAttributeMaxDynamicSharedMemorySize, SMEM_BYTES);
    rnn_cluster_kernel<<<16 * CLUSTER, NTHREADS, SMEM_BYTES>>>(
        u, inoise, rnoise, Wrec, brec, Win, out);
}

// round 12
// speedup vs baseline: 1.8710x; 1.8710x over previous
#include <cuda_runtime.h>

typedef unsigned long long ull;

#define BATCH    128
#define TSTEPS   512
#define NDIM     512
#define NIN      6

#define BG_COUNT 16      // batch groups (8 rows each)
#define NG_COUNT 8       // n groups (64 cols each) = producers per group
#define TILE_B   8
#define TILE_N   64
#define NTHREADS 288     // warps 0-7 compute (kh = w>>2), warp 8 = loader
#define K4       128     // 512/4 float4-chunks along k
#define CHUNK_BYTES 2048 // one producer's h block: 8 b x 64 n floats, swizzled

#define FLAG_STRIDE 16   // ull per flag slot = 128B line

#define W_OFF     0
#define W_BYTES   (K4 * TILE_N * 16)          // 131072
#define BUF_OFF   (W_OFF + W_BYTES)           // 2 x 16KB (parity), 8 chunks each
#define BUF_HALF  16384
#define RED_OFF   (BUF_OFF + 2 * BUF_HALF)    // 163840: 4 x 128 ull = 4096
#define V6_OFF    (RED_OFF + 4096)            // 167936: [8][8] floats
#define WINS_OFF  (V6_OFF + 256)              // 168192: [64][8] floats
#define BREC_OFF  (WINS_OFF + 2048)           // 170240: [64]
#define SHBASE_OFF (BREC_OFF + 256)           // 170496
#define MBAR_OFF  (SHBASE_OFF + 8)            // 170504: 16 mbars x 8B
#define SMEM_BYTES (MBAR_OFF + 128 + 56)

// Persistent scratch. g_hbuf: [parity][bg][chunk][2KB], chunk-contiguous, holds
// TF32-rounded h pre-swizzled: within block, addr = b*256 + ((k4l^b)<<4) + (n&3)*4.
__device__ float4 g_hbuf[2][BG_COUNT][NG_COUNT][CHUNK_BYTES / 16];
__device__ ull    g_flags[BG_COUNT * NG_COUNT * FLAG_STRIDE];

__device__ __forceinline__ void ffma2(ull &acc, ull a, ull b) {
    asm("fma.rn.f32x2 %0, %1, %2, %0;" : "+l"(acc) : "l"(a), "l"(b));
}
__device__ __forceinline__ float2 unpack2(ull v) {
    float2 r;
    asm("mov.b64 {%0,%1}, %2;" : "=f"(r.x), "=f"(r.y) : "l"(v));
    return r;
}
__device__ __forceinline__ float tf32r(float x) {
    float r;
    asm("cvt.rna.tf32.f32 %0, %1;" : "=f"(r) : "f"(x));
    return r;
}
__device__ __forceinline__ float4 tf32r4(float4 v) {
    v.x = tf32r(v.x); v.y = tf32r(v.y); v.z = tf32r(v.z); v.w = tf32r(v.w);
    return v;
}
__device__ __forceinline__ ull ld_acquire_gpu(const ull* p) {
    ull v;
    asm volatile("ld.acquire.gpu.global.b64 %0, [%1];" : "=l"(v) : "l"(p) : "memory");
    return v;
}
__device__ __forceinline__ void st_release_gpu(ull* p, ull v) {
    asm volatile("st.release.gpu.global.b64 [%0], %1;" :: "l"(p), "l"(v) : "memory");
}
__device__ __forceinline__ void mbar_init(unsigned mb, unsigned cnt) {
    asm volatile("mbarrier.init.shared.b64 [%0], %1;" :: "r"(mb), "r"(cnt) : "memory");
}
__device__ __forceinline__ void mbar_arm_tx(unsigned mb, unsigned tx) {
    asm volatile("mbarrier.arrive.expect_tx.shared.b64 _, [%0], %1;" :: "r"(mb), "r"(tx) : "memory");
}
__device__ __forceinline__ void mbar_wait_parity(unsigned mbar, unsigned parity) {
    unsigned done;
    asm volatile(
        "{\n\t.reg .pred p;\n\t"
        "mbarrier.try_wait.parity.acquire.cta.shared::cta.b64 p, [%1], %2;\n\t"
        "selp.b32 %0, 1, 0, p;\n\t}"
        : "=r"(done) : "r"(mbar), "r"(parity) : "memory");
    if (!done) {
        asm volatile(
            "{\n\t.reg .pred P1;\n\t"
            "WL_%=:\n\t"
            "mbarrier.try_wait.parity.acquire.cta.shared::cta.b64 P1, [%0], %1, 0x989680;\n\t"
            "@P1 bra.uni WD_%=;\n\t"
            "bra.uni WL_%=;\n\t"
            "WD_%=:\n\t}"
            :: "r"(mbar), "r"(parity) : "memory");
    }
}
__device__ __forceinline__ void bulk_copy_g2s(unsigned dst, ull src, unsigned bytes, unsigned mb) {
    asm volatile(
        "cp.async.bulk.shared::cluster.global.mbarrier::complete_tx::bytes [%0], [%1], %2, [%3];"
        :: "r"(dst), "l"(src), "r"(bytes), "r"(mb) : "memory");
}

__global__ void __launch_bounds__(NTHREADS, 1)
rnn_pipe_kernel(const float* __restrict__ u,
                const float* __restrict__ inoise,
                const float* __restrict__ rnoise,
                const float* __restrict__ Wrec,
                const float* __restrict__ brec,
                const float* __restrict__ Win,
                float* __restrict__ out)
{
    extern __shared__ char smem[];
    ulonglong2* Wq2  = (ulonglong2*)(smem + W_OFF);   // [K4][64] tf32-rounded
    float4*     Wq4  = (float4*)Wq2;
    ull*        redsm = (ull*)(smem + RED_OFF);       // [4][128]
    float*      v6   = (float*)(smem + V6_OFF);       // [8][8]
    float*      WinS = (float*)(smem + WINS_OFF);     // [64][8]
    float*      brecS= (float*)(smem + BREC_OFF);     // [64]
    ull*        shBase = (ull*)(smem + SHBASE_OFF);

    const int tid = threadIdx.x;
    const int bx  = blockIdx.x;
    const int bg  = bx >> 3;    // 0..15
    const int ng  = bx & 7;     // 0..7

    const unsigned smem_base = (unsigned)__cvta_generic_to_shared(smem);
    const unsigned mbar_base = smem_base + MBAR_OFF;  // mbar[q*8+c] at +8 each
    const unsigned buf_base  = smem_base + BUF_OFF;

    // ---------------- init: W slice (tf32), Win, brec, mbars, zero h_0 block ----------------
    const float4* WrecF4 = (const float4*)Wrec;
    for (int idx = tid; idx < TILE_N * K4; idx += NTHREADS) {
        int r = idx >> 7, k4 = idx & (K4 - 1);        // r = local n row 0..63
        Wq4[k4 * TILE_N + r] = tf32r4(__ldg(&WrecF4[(ng * TILE_N + r) * K4 + k4]));
    }
    for (int idx = tid; idx < TILE_N * NIN; idx += NTHREADS) {
        int r = idx / NIN, i = idx - r * NIN;
        WinS[r * 8 + i] = tf32r(Win[(ng * TILE_N + r) * NIN + i]);
    }
    if (tid < TILE_N) brecS[tid] = brec[ng * TILE_N + tid];
    if (tid < CHUNK_BYTES / 16)                       // zero own h_0 block (parity 0)
        g_hbuf[0][bg][ng][tid] = make_float4(0.f, 0.f, 0.f, 0.f);
    if (tid == 0) {
        shBase[0] = *((volatile ull*)&g_flags[bx * FLAG_STRIDE]);
        for (int m = 0; m < 16; ++m) mbar_init(mbar_base + m * 8, 1);
    }
    __syncthreads();
    const ull base = shBase[0];
    if (tid == 0) st_release_gpu(&g_flags[bx * FLAG_STRIDE], base + 1ull);   // h_0 published

    // compute-warp mapping (warps 0..7): wk = w&3 owns n [wk*16,+16); kh = w>>2 = k half.
    // lane: b = lane>>2 (0..7), ln = lane&3. Thread tile: 1b x 4n (n_l0,n_l0+1,n_l2,n_l2+1).
    const int w    = tid >> 5, lane = tid & 31;
    const int wk   = w & 3;
    const int kh   = w >> 2;                          // 0,1 (compute); w==8 loader
    const int b    = lane >> 2;
    const int ln   = lane & 3;
    const int n_l0 = wk * 16 + 2 * ln;
    const int n_l2 = n_l0 + 8;
    const int bG   = bg * TILE_B + b;
    const int nG0  = ng * TILE_N + n_l0;
    const int nG2  = nG0 + 8;
    const int slot = wk * 32 + lane;

    const bool is_compute = (w < 8);
    const bool is_kh0     = (w < 4);

    // producer publish offsets inside own block (pre-swizzled for consumer LDS)
    const int k4l_0 = n_l0 >> 2, k4l_2 = n_l2 >> 2;
    const int po0 = b * 256 + (((k4l_0) ^ b) << 4) + (n_l0 & 3) * 4;
    const int po2 = b * 256 + (((k4l_2) ^ b) << 4) + (n_l2 & 3) * 4;
    const ull g_h_base = (ull)__cvta_generic_to_global(&g_hbuf[0][0][0][0]);

    // out[:, 0, :] = 0
    if (is_kh0) {
        float2 z = make_float2(0.f, 0.f);
        ((float2*)out)[(((size_t)bG * TSTEPS) * NDIM + nG0) >> 1] = z;
        ((float2*)out)[(((size_t)bG * TSTEPS) * NDIM + nG2) >> 1] = z;
    }

    float hp0 = 0.f, hp1 = 0.f, hp2 = 0.f, hp3 = 0.f;   // exact h_{s-1} (leak term)

    for (int s = 1; s < TSTEPS; ++s) {
        const int q  = (s - 1) & 1;                   // data-parity (h_{s-1} image / buffers)
        const unsigned ph = (unsigned)(((s - 1) >> 1) & 1);  // mbar phase parity for set q

        float2 rn01, rn23;
        if (is_kh0) {
            rn01 = __ldg((const float2*)(rnoise + ((size_t)bG * TSTEPS + (s - 1)) * NDIM + nG0));
            rn23 = __ldg((const float2*)(rnoise + ((size_t)bG * TSTEPS + (s - 1)) * NDIM + nG2));
        }
        if (tid < TILE_B * NIN) {                     // 48 threads (warps 0-1, kh0)
            int r = tid / NIN, i = tid - r * NIN;
            int gi = ((bg * TILE_B + r) * TSTEPS + (s - 1)) * NIN + i;
            v6[r * 8 + i] = tf32r(__ldg(&u[gi]) + 0.6324555320336759f * __ldg(&inoise[gi]));
        }

        if (w == 8) {
            // ---- loader: per-chunk arm -> poll producer flag -> 2KB bulk copy ----
            if (lane < NG_COUNT) {
                unsigned mb = mbar_base + (unsigned)((q * 8 + lane) << 3);
                mbar_arm_tx(mb, CHUNK_BYTES);
                const ull* f = &g_flags[(bg * NG_COUNT + lane) * FLAG_STRIDE];
                ull target = base + (ull)s;
                while (ld_acquire_gpu(f) < target) {}
                asm volatile("fence.proxy.async;" ::: "memory");
                ull src = g_h_base + (ull)(((q * BG_COUNT + bg) * NG_COUNT + lane) * CHUNK_BYTES);
                unsigned dst = buf_base + (unsigned)(q * BUF_HALF + lane * CHUNK_BYTES);
                bulk_copy_g2s(dst, src, CHUNK_BYTES, mb);
            }
            __syncwarp();
        }

        ull a0 = 0ull, a1 = 0ull, a2 = 0ull, a3 = 0ull;
        if (is_compute) {
            // ---- GEMM: 4 chunks of this k-half, waiting each chunk's mbar ----
            const char* bufq = smem + BUF_OFF + q * BUF_HALF;
            #pragma unroll 1
            for (int c = kh * 4; c < kh * 4 + 4; ++c) {
                mbar_wait_parity(mbar_base + (unsigned)((q * 8 + c) << 3), ph);
                const char* hc = bufq + c * CHUNK_BYTES + b * 256;
                const ulonglong2* Wc = Wq2 + (c * 16) * TILE_N;
                #pragma unroll
                for (int k4l = 0; k4l < 16; ++k4l) {
                    ulonglong2 h = *(const ulonglong2*)(hc + (((k4l ^ b)) << 4));
                    const ulonglong2* wrow = Wc + k4l * TILE_N;
                    ulonglong2 w0 = wrow[n_l0];
                    ulonglong2 w1 = wrow[n_l0 + 1];
                    ulonglong2 w2 = wrow[n_l2];
                    ulonglong2 w3 = wrow[n_l2 + 1];
                    ffma2(a0, h.x, w0.x); ffma2(a0, h.y, w0.y);
                    ffma2(a1, h.x, w1.x); ffma2(a1, h.y, w1.y);
                    ffma2(a2, h.x, w2.x); ffma2(a2, h.y, w2.y);
                    ffma2(a3, h.x, w3.x); ffma2(a3, h.y, w3.y);
                }
            }
            if (kh == 1) {
                redsm[0 * 128 + slot] = a0;
                redsm[1 * 128 + slot] = a1;
                redsm[2 * 128 + slot] = a2;
                redsm[3 * 128 + slot] = a3;
            }
        }
        __syncthreads();                               // redsm ready

        if (is_kh0) {
            float2 s0 = unpack2(a0), p0 = unpack2(redsm[0 * 128 + slot]);
            float2 s1 = unpack2(a1), p1 = unpack2(redsm[1 * 128 + slot]);
            float2 s2 = unpack2(a2), p2 = unpack2(redsm[2 * 128 + slot]);
            float2 s3 = unpack2(a3), p3 = unpack2(redsm[3 * 128 + slot]);
            float acc0 = (s0.x + s0.y) + (p0.x + p0.y);
            float acc1 = (s1.x + s1.y) + (p1.x + p1.y);
            float acc2 = (s2.x + s2.y) + (p2.x + p2.y);
            float acc3 = (s3.x + s3.y) + (p3.x + p3.y);

            float in0 = 0.f, in1 = 0.f, in2 = 0.f, in3 = 0.f;
            #pragma unroll
            for (int i = 0; i < NIN; ++i) {
                float vb = v6[b * 8 + i];
                in0 += vb * WinS[n_l0 * 8 + i];
                in1 += vb * WinS[(n_l0 + 1) * 8 + i];
                in2 += vb * WinS[n_l2 * 8 + i];
                in3 += vb * WinS[(n_l2 + 1) * 8 + i];
            }

            float pre0 = (acc0 + brecS[n_l0])     + in0;
            float pre1 = (acc1 + brecS[n_l0 + 1]) + in1;
            float pre2 = (acc2 + brecS[n_l2])     + in2;
            float pre3 = (acc3 + brecS[n_l2 + 1]) + in3;
            float h0 = 0.8f * hp0 + 0.2f * (fmaxf(pre0, 0.f) + rn01.x);
            float h1 = 0.8f * hp1 + 0.2f * (fmaxf(pre1, 0.f) + rn01.y);
            float h2 = 0.8f * hp2 + 0.2f * (fmaxf(pre2, 0.f) + rn23.x);
            float h3 = 0.8f * hp3 + 0.2f * (fmaxf(pre3, 0.f) + rn23.y);
            hp0 = h0; hp1 = h1; hp2 = h2; hp3 = h3;

            // publish TF32-rounded h_s into own chunk block (parity s&1)
            char* pb = (char*)&g_hbuf[0][0][0][0]
                     + (size_t)((((s & 1) * BG_COUNT + bg) * NG_COUNT + ng) * CHUNK_BYTES);
            *(float2*)(pb + po0) = make_float2(tf32r(h0), tf32r(h1));
            *(float2*)(pb + po2) = make_float2(tf32r(h2), tf32r(h3));
        }
        __syncthreads();                               // all h stores done CTA-wide
        if (tid == 0)
            st_release_gpu(&g_flags[bx * FLAG_STRIDE], base + (ull)s + 1ull);

        if (is_kh0) {
            // out write AFTER the release — off the inter-CTA critical path
            float2* odst = (float2*)out;
            odst[(((size_t)bG * TSTEPS + s) * NDIM + nG0) >> 1] =
                make_float2(hp0, hp1);
            odst[(((size_t)bG * TSTEPS + s) * NDIM + nG2) >> 1] =
                make_float2(hp2, hp3);
        }
    }
}

extern "C" void kernel_launch(void* const* d_in, const int* in_sizes, int n_in,
                              void* d_out, int out_size) {
    const float* u      = (const float*)d_in[0];
    const float* inoise = (const float*)d_in[1];
    const float* rnoise = (const float*)d_in[2];
    const float* Wrec   = (const float*)d_in[3];
    const float* brec   = (const float*)d_in[4];
    const float* Win    = (const float*)d_in[5];
    float* out = (float*)d_out;

    cudaFuncSetAttribute(rnn_pipe_kernel,
                         cudaFuncAttributeMaxDynamicSharedMemorySize, SMEM_BYTES);
    rnn_pipe_kernel<<<BG_COUNT * NG_COUNT, NTHREADS, SMEM_BYTES>>>(
        u, inoise, rnoise, Wrec, brec, Win, out);
}

// round 17
// speedup vs baseline: 2.0116x; 1.0752x over previous
#include <cuda_runtime.h>

typedef unsigned long long ull;

#define TSTEPS   512
#define NDIM     512
#define NIN      6
#define NPAIR    16      // pair p owns batch rows [8p, 8p+8): A=[8p,8p+4), B=[8p+4,8p+8)
#define NGC      8       // n-groups (producers per dependency group)
#define TILE_N   64
#define NTHREADS 288     // warps 0-7 compute (wk=w&3, kh=w>>2), warp 8 loader
#define K4       128
#define FLAG_STRIDE 16   // ull per flag = 128B line

#define W_BYTES    (K4 * TILE_N * 16)       // 131072
#define BUFA_OFF   (W_BYTES)                // 2 x 8KB (parity)
#define BUFB_OFF   (BUFA_OFF + 2 * 8192)
#define RED_OFF    (BUFB_OFF + 2 * 8192)    // 2KB (2 x 128 ull)
#define SHBASE_OFF (RED_OFF + 2048)
#define MBAR_OFF   (SHBASE_OFF + 8)         // mbA[2],mbB[2],dnA[2],dnB[2] @ 8B each
#define SMEM_BYTES (MBAR_OFF + 96)

// h image: [parity][pair][group][4 rows][128 slots] float4, pre-swizzled slot=(k4^b)
__device__ float4 g_hbuf[2][NPAIR][2][4 * K4];
__device__ ull    g_flags[NPAIR * NGC * 2 * FLAG_STRIDE];   // monotonic

__device__ __forceinline__ void ffma2(ull &acc, ull a, ull b) {
    asm("fma.rn.f32x2 %0, %1, %2, %0;" : "+l"(acc) : "l"(a), "l"(b));
}
__device__ __forceinline__ float2 unpack2(ull v) {
    float2 r;
    asm("mov.b64 {%0,%1}, %2;" : "=f"(r.x), "=f"(r.y) : "l"(v));
    return r;
}
__device__ __forceinline__ float tf32r(float x) {
    float r;
    asm("cvt.rna.tf32.f32 %0, %1;" : "=f"(r) : "f"(x));
    return r;
}
__device__ __forceinline__ float4 tf32r4(float4 v) {
    v.x = tf32r(v.x); v.y = tf32r(v.y); v.z = tf32r(v.z); v.w = tf32r(v.w);
    return v;
}
__device__ __forceinline__ ull ld_acquire_gpu(const ull* p) {
    ull v;
    asm volatile("ld.acquire.gpu.global.b64 %0, [%1];" : "=l"(v) : "l"(p) : "memory");
    return v;
}
__device__ __forceinline__ void st_release_gpu(ull* p, ull v) {
    asm volatile("st.release.gpu.global.b64 [%0], %1;" :: "l"(p), "l"(v) : "memory");
}
__device__ __forceinline__ void mbar_init(unsigned mb, unsigned cnt) {
    asm volatile("mbarrier.init.shared.b64 [%0], %1;" :: "r"(mb), "r"(cnt) : "memory");
}
__device__ __forceinline__ void mbar_arm_tx(unsigned mb, unsigned tx) {
    asm volatile("mbarrier.arrive.expect_tx.shared.b64 _, [%0], %1;" :: "r"(mb), "r"(tx) : "memory");
}
__device__ __forceinline__ void mbar_arrive(unsigned mb) {
    asm volatile("mbarrier.arrive.shared.b64 _, [%0];" :: "r"(mb) : "memory");
}
__device__ __forceinline__ void mbar_wait_parity(unsigned mbar, unsigned parity) {
    unsigned done;
    asm volatile(
        "{\n\t.reg .pred p;\n\t"
        "mbarrier.try_wait.parity.acquire.cta.shared::cta.b64 p, [%1], %2;\n\t"
        "selp.b32 %0, 1, 0, p;\n\t}"
        : "=r"(done) : "r"(mbar), "r"(parity) : "memory");
    if (!done) {
        asm volatile(
            "{\n\t.reg .pred P1;\n\t"
            "WL_%=:\n\t"
            "mbarrier.try_wait.parity.acquire.cta.shared::cta.b64 P1, [%0], %1, 0x989680;\n\t"
            "@P1 bra.uni WD_%=;\n\t"
            "bra.uni WL_%=;\n\t"
            "WD_%=:\n\t}"
            :: "r"(mbar), "r"(parity) : "memory");
    }
}
__device__ __forceinline__ void bulk_copy_g2s(unsigned dst, ull src, unsigned bytes, unsigned mb) {
    asm volatile(
        "cp.async.bulk.shared::cluster.global.mbarrier::complete_tx::bytes [%0], [%1], %2, [%3];"
        :: "r"(dst), "l"(src), "r"(bytes), "r"(mb) : "memory");
}
__device__ __forceinline__ void barc() {   // compute-warps-only barrier
    asm volatile("bar.sync 1, 256;" ::: "memory");
}

__global__ void __launch_bounds__(NTHREADS, 1)
rnn_ab_kernel(const float* __restrict__ u,
              const float* __restrict__ inoise,
              const float* __restrict__ rnoise,
              const float* __restrict__ Wrec,
              const float* __restrict__ brec,
              const float* __restrict__ Win,
              float* __restrict__ out)
{
    extern __shared__ char smem[];
    ulonglong2* Wq2  = (ulonglong2*)smem;            // interleaved per-warp layout (below)
    float4*     Wq4  = (float4*)smem;
    ull*        redsm = (ull*)(smem + RED_OFF);      // [2][128]
    ull*        shBase = (ull*)(smem + SHBASE_OFF);

    const int tid = threadIdx.x;
    const int bx  = blockIdx.x;
    const int p   = bx >> 3;     // pair 0..15
    const int ng  = bx & 7;      // 0..7

    const unsigned smem_base = (unsigned)__cvta_generic_to_shared(smem);
    const unsigned mbA  = smem_base + MBAR_OFF;      // +0,+8
    const unsigned mbB  = mbA + 16;                  // +16,+24
    const unsigned dnA  = mbA + 32;                  // +32,+40
    const unsigned dnB  = mbA + 48;                  // +48,+56
    const unsigned bufA_sm = smem_base + BUFA_OFF;
    const unsigned bufB_sm = smem_base + BUFB_OFF;

    // ---- init: W slice (tf32, warp-interleaved: dst = k4*64 + wk*16 + odd*8 + ln) ----
    const float4* WrecF4 = (const float4*)Wrec;
    for (int idx = tid; idx < TILE_N * K4; idx += NTHREADS) {
        int r = idx >> 7, k4 = idx & (K4 - 1);       // r = local n 0..63
        int dst = k4 * 64 + (r >> 4) * 16 + (r & 1) * 8 + ((r >> 1) & 7);
        Wq4[dst] = tf32r4(__ldg(&WrecF4[(ng * TILE_N + r) * K4 + k4]));
    }
    // zero bufA[0], bufB[0] (h_0)
    for (int idx = tid; idx < 2 * 8192 / 16; idx += NTHREADS) {
        ((float4*)(smem + BUFA_OFF))[idx] = make_float4(0.f, 0.f, 0.f, 0.f);
        ((float4*)(smem + BUFB_OFF))[idx] = make_float4(0.f, 0.f, 0.f, 0.f);
    }
    if (tid == 0) {
        shBase[0] = *((volatile ull*)&g_flags[((p * NGC + ng) * 2 + 0) * FLAG_STRIDE]);
        mbar_init(mbA + 0, 1); mbar_init(mbA + 8, 1);
        mbar_init(mbB + 0, 1); mbar_init(mbB + 8, 1);
        mbar_init(dnA + 0, 8); mbar_init(dnA + 8, 8);
        mbar_init(dnB + 0, 8); mbar_init(dnB + 8, 8);
    }
    __syncthreads();
    const ull base = shBase[0];

    const int w    = tid >> 5, lane = tid & 31;
    const int wk   = w & 3;
    const int kh   = w >> 2;                          // 0/1 compute halves; w==8 loader
    const int b    = lane >> 3;                       // 0..3 group-local row
    const int ln   = lane & 7;
    const int n_l0 = wk * 16 + 2 * ln;
    const int nG0  = ng * TILE_N + n_l0;
    const int bGA  = p * 8 + b;
    const int bGB  = p * 8 + 4 + b;
    const int slot = wk * 32 + lane;

    const ull g_h_base = (ull)__cvta_generic_to_global(&g_hbuf[0][0][0][0]);
    ull* flagA_own = &g_flags[((p * NGC + ng) * 2 + 0) * FLAG_STRIDE];
    ull* flagB_own = &g_flags[((p * NGC + ng) * 2 + 1) * FLAG_STRIDE];

    if (w == 8) {
        // ================= loader warp =================
        int cA[2] = {0, 0}, cB[2] = {0, 0};
        for (int s = 2; s < TSTEPS; ++s) {
            int x = (s - 1) & 1;
            // ---- group A: recycle buf, poll flags, copy 8KB ----
            if (s > 2) {
                if (lane == 0) { mbar_wait_parity(dnA + (x << 3), (unsigned)cA[x]); cA[x] ^= 1; }
                __syncwarp();
            }
            if (lane < NGC) {
                const ull* f = &g_flags[((p * NGC + lane) * 2 + 0) * FLAG_STRIDE];
                ull tgt = base + (ull)(s - 1);
                while (ld_acquire_gpu(f) < tgt) {}
            }
            __syncwarp();
            if (lane == 0) {
                asm volatile("fence.proxy.async;" ::: "memory");
                mbar_arm_tx(mbA + (x << 3), 8192u);
                bulk_copy_g2s(bufA_sm + (unsigned)(x * 8192),
                              g_h_base + (ull)(((x * NPAIR + p) * 2 + 0) * 8192),
                              8192u, mbA + (x << 3));
            }
            // ---- group B ----
            if (s > 2) {
                if (lane == 0) { mbar_wait_parity(dnB + (x << 3), (unsigned)cB[x]); cB[x] ^= 1; }
                __syncwarp();
            }
            if (lane < NGC) {
                const ull* f = &g_flags[((p * NGC + lane) * 2 + 1) * FLAG_STRIDE];
                ull tgt = base + (ull)(s - 1);
                while (ld_acquire_gpu(f) < tgt) {}
            }
            __syncwarp();
            if (lane == 0) {
                asm volatile("fence.proxy.async;" ::: "memory");
                mbar_arm_tx(mbB + (x << 3), 8192u);
                bulk_copy_g2s(bufB_sm + (unsigned)(x * 8192),
                              g_h_base + (ull)(((x * NPAIR + p) * 2 + 1) * 8192),
                              8192u, mbB + (x << 3));
            }
        }
        return;
    }

    // ================= compute warps =================
    // constants in registers
    float win0[NIN], win1[NIN], br0 = 0.f, br1 = 0.f;
    #pragma unroll
    for (int i = 0; i < NIN; ++i) {
        win0[i] = tf32r(__ldg(&Win[nG0 * NIN + i]));
        win1[i] = tf32r(__ldg(&Win[(nG0 + 1) * NIN + i]));
    }
    br0 = __ldg(&brec[nG0]); br1 = __ldg(&brec[nG0 + 1]);

    // out[:,0,:] = 0
    if (kh == 0) {
        float2 z = make_float2(0.f, 0.f);
        ((float2*)out)[(((size_t)bGA * TSTEPS) * NDIM + nG0) >> 1] = z;
        ((float2*)out)[(((size_t)bGB * TSTEPS) * NDIM + nG0) >> 1] = z;
    }

    // publish byte offsets inside a [4][128] float4 block
    const int pubo = b * 2048 + ((((nG0 >> 2) ^ b)) << 4) + (nG0 & 3) * 4;

    int qA[2] = {0, 0}, qB[2] = {0, 0};
    float hpA0 = 0.f, hpA1 = 0.f, hpB0 = 0.f, hpB1 = 0.f;
    const float NSCALE = 0.6324555320336759f;

    #define GEMM_HALF(BUFOFF, x, A0, A1) do {                                   \
        const char* hb = smem + (BUFOFF) + (x) * 8192 + b * 2048 + kh * 1024;   \
        const ulonglong2* Wk = Wq2 + (kh * 64) * 64 + wk * 16;                  \
        _Pragma("unroll 8")                                                     \
        for (int j = 0; j < 64; ++j) {                                          \
            ulonglong2 h  = *(const ulonglong2*)(hb + ((j ^ b) << 4));          \
            ulonglong2 w0 = Wk[j * 64 + ln];                                    \
            ulonglong2 w1 = Wk[j * 64 + 8 + ln];                                \
            ffma2(A0, h.x, w0.x); ffma2(A0, h.y, w0.y);                         \
            ffma2(A1, h.x, w1.x); ffma2(A1, h.y, w1.y);                         \
        }                                                                       \
    } while (0)

    for (int s = 1; s < TSTEPS; ++s) {
        const int x = (s - 1) & 1;

        // ---- A inputs (independent of h) ----
        float2 rnA; float vA[NIN];
        if (kh == 0) {
            rnA = __ldg((const float2*)(rnoise + ((size_t)bGA * TSTEPS + (s - 1)) * NDIM + nG0));
            const float* ua = u      + ((size_t)bGA * TSTEPS + (s - 1)) * NIN;
            const float* na = inoise + ((size_t)bGA * TSTEPS + (s - 1)) * NIN;
            #pragma unroll
            for (int i = 0; i < NIN; ++i) vA[i] = tf32r(__ldg(&ua[i]) + NSCALE * __ldg(&na[i]));
        }
        if (s > 1) { mbar_wait_parity(mbA + (x << 3), (unsigned)qA[x]); qA[x] ^= 1; }

        ull a0 = 0ull, a1 = 0ull;
        GEMM_HALF(BUFA_OFF, x, a0, a1);
        if (lane == 0) mbar_arrive(dnA + (x << 3));
        if (kh == 1) { redsm[slot] = a0; redsm[128 + slot] = a1; }
        barc();
        float hA0, hA1;
        if (kh == 0) {
            float2 e0 = unpack2(a0), p0 = unpack2(redsm[slot]);
            float2 e1 = unpack2(a1), p1 = unpack2(redsm[128 + slot]);
            float acc0 = (e0.x + e0.y) + (p0.x + p0.y);
            float acc1 = (e1.x + e1.y) + (p1.x + p1.y);
            float in0 = 0.f, in1 = 0.f;
            #pragma unroll
            for (int i = 0; i < NIN; ++i) { in0 += vA[i] * win0[i]; in1 += vA[i] * win1[i]; }
            float pre0 = (acc0 + br0) + in0;
            float pre1 = (acc1 + br1) + in1;
            hA0 = 0.8f * hpA0 + 0.2f * (fmaxf(pre0, 0.f) + rnA.x);
            hA1 = 0.8f * hpA1 + 0.2f * (fmaxf(pre1, 0.f) + rnA.y);
            hpA0 = hA0; hpA1 = hA1;
            char* pb = (char*)&g_hbuf[0][0][0][0]
                     + (size_t)((((s & 1) * NPAIR + p) * 2 + 0) * 8192) + pubo;
            *(float2*)pb = make_float2(tf32r(hA0), tf32r(hA1));
        }
        barc();
        if (tid == 0) st_release_gpu(flagA_own, base + (ull)s);

        // ---- B inputs ----
        float2 rnB; float vB[NIN];
        if (kh == 0) {
            rnB = __ldg((const float2*)(rnoise + ((size_t)bGB * TSTEPS + (s - 1)) * NDIM + nG0));
            const float* ub = u      + ((size_t)bGB * TSTEPS + (s - 1)) * NIN;
            const float* nb = inoise + ((size_t)bGB * TSTEPS + (s - 1)) * NIN;
            #pragma unroll
            for (int i = 0; i < NIN; ++i) vB[i] = tf32r(__ldg(&ub[i]) + NSCALE * __ldg(&nb[i]));
        }
        if (s > 1) { mbar_wait_parity(mbB + (x << 3), (unsigned)qB[x]); qB[x] ^= 1; }

        ull c0 = 0ull, c1 = 0ull;
        GEMM_HALF(BUFB_OFF, x, c0, c1);
        if (lane == 0) mbar_arrive(dnB + (x << 3));
        if (kh == 1) { redsm[slot] = c0; redsm[128 + slot] = c1; }
        barc();
        if (kh == 0) {
            float2 e0 = unpack2(c0), p0 = unpack2(redsm[slot]);
            float2 e1 = unpack2(c1), p1 = unpack2(redsm[128 + slot]);
            float acc0 = (e0.x + e0.y) + (p0.x + p0.y);
            float acc1 = (e1.x + e1.y) + (p1.x + p1.y);
            float in0 = 0.f, in1 = 0.f;
            #pragma unroll
            for (int i = 0; i < NIN; ++i) { in0 += vB[i] * win0[i]; in1 += vB[i] * win1[i]; }
            float pre0 = (acc0 + br0) + in0;
            float pre1 = (acc1 + br1) + in1;
            float hB0 = 0.8f * hpB0 + 0.2f * (fmaxf(pre0, 0.f) + rnB.x);
            float hB1 = 0.8f * hpB1 + 0.2f * (fmaxf(pre1, 0.f) + rnB.y);
            hpB0 = hB0; hpB1 = hB1;
            char* pb = (char*)&g_hbuf[0][0][0][0]
                     + (size_t)((((s & 1) * NPAIR + p) * 2 + 1) * 8192) + pubo;
            *(float2*)pb = make_float2(tf32r(hB0), tf32r(hB1));
        }
        barc();
        if (tid == 0) st_release_gpu(flagB_own, base + (ull)s);

        // ---- out writes (off the critical path) ----
        if (kh == 0) {
            float2* odst = (float2*)out;
            odst[(((size_t)bGA * TSTEPS + s) * NDIM + nG0) >> 1] = make_float2(hpA0, hpA1);
            odst[(((size_t)bGB * TSTEPS + s) * NDIM + nG0) >> 1] = make_float2(hpB0, hpB1);
        }
    }
    #undef GEMM_HALF
}

extern "C" void kernel_launch(void* const* d_in, const int* in_sizes, int n_in,
                              void* d_out, int out_size) {
    const float* u      = (const float*)d_in[0];
    const float* inoise = (const float*)d_in[1];
    const float* rnoise = (const float*)d_in[2];
    const float* Wrec   = (const float*)d_in[3];
    const float* brec   = (const float*)d_in[4];
    const float* Win    = (const float*)d_in[5];
    float* out = (float*)d_out;

    cudaFuncSetAttribute(rnn_ab_kernel,
                         cudaFuncAttributeMaxDynamicSharedMemorySize, SMEM_BYTES);
    rnn_ab_kernel<<<NPAIR * NGC, NTHREADS, SMEM_BYTES>>>(
        u, inoise, rnoise, Wrec, brec, Win, out);
}